// round 1
// baseline (speedup 1.0000x reference)
#include <cuda_runtime.h>
#include <math.h>

// ---------------------------------------------------------------------------
// VQ-VAE VectorQuantizer forward:
//  z_e (32,64,32,32) f32, codebook (1024,64) f32
//  out = [ z_q_st (2097152) | vq_loss (1) | indices (32768) | perplexity (1) | usage (1024) ]
// ---------------------------------------------------------------------------

#define D_DIM   64
#define KCODES  1024
#define HW      1024
#define TM      128          // pixels per CTA tile
#define KC      128          // codes per chunk
#define NCHUNK  (KCODES / KC)
#define NTILES  256          // 32768 / TM
#define NPIX    32768
#define ZQ_ELEMS 2097152

#define OFS_LOSS  2097152
#define OFS_IDX   2097153
#define OFS_PPL   2129921
#define OFS_USAGE 2129922

__device__ int   g_counts[KCODES];
__device__ float g_e2[KCODES];
__device__ float g_sse;

// ---- packed f32x2 helpers --------------------------------------------------
__device__ __forceinline__ unsigned long long pack2(float x, float y) {
    unsigned long long r;
    asm("mov.b64 %0, {%1, %2};" : "=l"(r) : "f"(x), "f"(y));
    return r;
}
__device__ __forceinline__ void fma2(unsigned long long& d,
                                     unsigned long long a,
                                     unsigned long long b) {
    asm("fma.rn.f32x2 %0, %1, %2, %0;" : "+l"(d) : "l"(a), "l"(b));
}
__device__ __forceinline__ float2 unpack2(unsigned long long v) {
    float2 f;
    asm("mov.b64 {%0, %1}, %2;" : "=f"(f.x), "=f"(f.y) : "l"(v));
    return f;
}

// ---------------------------------------------------------------------------
// Kernel 1: per-code squared norms + zero global accumulators
// ---------------------------------------------------------------------------
__global__ void vq_prep(const float* __restrict__ cb) {
    int k = blockIdx.x * blockDim.x + threadIdx.x;
    if (k < KCODES) {
        const float* row = cb + (size_t)k * D_DIM;
        float s = 0.f;
#pragma unroll
        for (int d = 0; d < D_DIM; ++d) s = fmaf(row[d], row[d], s);
        g_e2[k] = s;
        g_counts[k] = 0;
        if (k == 0) g_sse = 0.f;
    }
}

// ---------------------------------------------------------------------------
// Kernel 2: main — distances, argmin, z_q gather, transposed store, stats
// ---------------------------------------------------------------------------
struct SmemLayout {
    float z_s[D_DIM][TM + 4];     // z tile, [d][p], padded rows (16B-aligned)
    float e_s[D_DIM][KC + 4];     // codebook chunk, [d][k]; reused as z_q staging
    float z2_s[TM];
    float e2_s[KC];
    float red_d[8][TM];
    int   red_i[8][TM];
    int   idx_s[TM];
    int   cnt_s[KCODES];
};

__global__ void __launch_bounds__(256, 2)
vq_main(const float* __restrict__ ze, const float* __restrict__ cb,
        float* __restrict__ out) {
    extern __shared__ __align__(16) char smem_raw[];
    SmemLayout* sm = reinterpret_cast<SmemLayout*>(smem_raw);

    const int tid  = threadIdx.x;
    const int tile = blockIdx.x;
    const int b    = tile >> 3;            // 8 tiles per batch image
    const int hw0  = (tile & 7) * TM;
    const float* zbase = ze + (size_t)b * D_DIM * HW + hw0;

    // zero histogram
    for (int i = tid; i < KCODES; i += 256) sm->cnt_s[i] = 0;

    // load z tile (coalesced over hw)
    for (int f = tid; f < D_DIM * TM; f += 256) {
        int d = f >> 7, p = f & 127;
        sm->z_s[d][p] = zbase[d * HW + p];
    }
    __syncthreads();

    // per-pixel squared norm (fp32 sequential; integer-ulp shifts don't affect argmin)
    if (tid < TM) {
        float s = 0.f;
#pragma unroll
        for (int d = 0; d < D_DIM; ++d) s = fmaf(sm->z_s[d][tid], sm->z_s[d][tid], s);
        sm->z2_s[tid] = s;
    }
    __syncthreads();

    const int pcol  = tid & 15;
    const int krow  = tid >> 4;
    const int p0    = pcol * 8;
    const int kloc0 = krow * 8;

    float z2r[8];
#pragma unroll
    for (int j = 0; j < 8; ++j) z2r[j] = sm->z2_s[p0 + j];

    float bestd[8];
    int   besti[8];
#pragma unroll
    for (int j = 0; j < 8; ++j) { bestd[j] = 3.4e38f; besti[j] = 0; }

    const int r_load = tid >> 1;           // code row this thread stages
    const int h_load = tid & 1;            // which 32-dim half

    for (int c = 0; c < NCHUNK; ++c) {
        const int kb = c * KC;
        if (c) __syncthreads();            // previous chunk's e_s reads done

        // ---- stage codebook chunk, transposed to [d][k] ----
        {
            const float4* src = reinterpret_cast<const float4*>(
                                    cb + (size_t)(kb + r_load) * D_DIM) + h_load * 8;
#pragma unroll
            for (int i = 0; i < 8; ++i) {
                float4 v = src[i];
                int d0 = h_load * 32 + i * 4;
                sm->e_s[d0 + 0][r_load] = v.x;
                sm->e_s[d0 + 1][r_load] = v.y;
                sm->e_s[d0 + 2][r_load] = v.z;
                sm->e_s[d0 + 3][r_load] = v.w;
            }
            if (tid < KC) sm->e2_s[tid] = g_e2[kb + tid];
        }
        __syncthreads();

        // ---- accumulate dot products: 8 px × 8 codes, packed over code pairs ----
        unsigned long long acc[8][4];
#pragma unroll
        for (int j = 0; j < 8; ++j)
#pragma unroll
            for (int kk = 0; kk < 4; ++kk) acc[j][kk] = 0ull;

#pragma unroll 16
        for (int d = 0; d < D_DIM; ++d) {
            ulonglong2 eA = *reinterpret_cast<const ulonglong2*>(&sm->e_s[d][kloc0]);
            ulonglong2 eB = *reinterpret_cast<const ulonglong2*>(&sm->e_s[d][kloc0 + 4]);
            float4 za = *reinterpret_cast<const float4*>(&sm->z_s[d][p0]);
            float4 zb = *reinterpret_cast<const float4*>(&sm->z_s[d][p0 + 4]);
            float zr[8] = {za.x, za.y, za.z, za.w, zb.x, zb.y, zb.z, zb.w};
#pragma unroll
            for (int j = 0; j < 8; ++j) {
                unsigned long long zz = pack2(zr[j], zr[j]);
                fma2(acc[j][0], zz, eA.x);
                fma2(acc[j][1], zz, eA.y);
                fma2(acc[j][2], zz, eB.x);
                fma2(acc[j][3], zz, eB.y);
            }
        }

        // ---- epilogue: exact JAX rounding, strict-< keeps first min ----
        float e2r[8];
#pragma unroll
        for (int kk = 0; kk < 8; ++kk) e2r[kk] = sm->e2_s[kloc0 + kk];

#pragma unroll
        for (int j = 0; j < 8; ++j) {
            float a = z2r[j];
#pragma unroll
            for (int kk = 0; kk < 4; ++kk) {
                float2 s = unpack2(acc[j][kk]);
                float d0 = fmaf(-2.f, s.x, a + e2r[kk * 2]);
                float d1 = fmaf(-2.f, s.y, a + e2r[kk * 2 + 1]);
                int k0 = kb + kloc0 + kk * 2;
                if (d0 < bestd[j]) { bestd[j] = d0; besti[j] = k0; }
                if (d1 < bestd[j]) { bestd[j] = d1; besti[j] = k0 + 1; }
            }
        }
    }

    // ---- cross-thread argmin: lexicographic (dist, index) min over 16 krows ----
#pragma unroll
    for (int j = 0; j < 8; ++j) {
        float od = __shfl_xor_sync(0xffffffffu, bestd[j], 16);
        int   oi = __shfl_xor_sync(0xffffffffu, besti[j], 16);
        if (od < bestd[j] || (od == bestd[j] && oi < besti[j])) {
            bestd[j] = od; besti[j] = oi;
        }
    }
    const int w = tid >> 5;
    if ((tid & 16) == 0) {
#pragma unroll
        for (int j = 0; j < 8; ++j) {
            sm->red_d[w][p0 + j] = bestd[j];
            sm->red_i[w][p0 + j] = besti[j];
        }
    }
    __syncthreads();

    if (tid < TM) {
        float bd = sm->red_d[0][tid];
        int   bi = sm->red_i[0][tid];
#pragma unroll
        for (int w2 = 1; w2 < 8; ++w2) {
            float d2 = sm->red_d[w2][tid];
            int   i2 = sm->red_i[w2][tid];
            if (d2 < bd || (d2 == bd && i2 < bi)) { bd = d2; bi = i2; }
        }
        sm->idx_s[tid] = bi;
        out[OFS_IDX + tile * TM + tid] = (float)bi;
        atomicAdd(&sm->cnt_s[bi], 1);
    }
    __syncthreads();

    // flush histogram
    for (int i = tid; i < KCODES; i += 256) {
        int cnum = sm->cnt_s[i];
        if (cnum) atomicAdd(&g_counts[i], cnum);
    }

    // ---- gather z_q, build z_q_st with JAX's rounding, SSE; stage in e_s ----
    {
        int p = tid >> 1, h = tid & 1;
        int ci = sm->idx_s[p];
        const float4* crow = reinterpret_cast<const float4*>(
                                 cb + (size_t)ci * D_DIM) + h * 8;
        float ssel = 0.f;
#pragma unroll
        for (int i = 0; i < 8; ++i) {
            float4 v = crow[i];
            int d0 = h * 32 + i * 4;
            float vv[4] = {v.x, v.y, v.z, v.w};
#pragma unroll
            for (int cc = 0; cc < 4; ++cc) {
                int d = d0 + cc;
                float zev  = sm->z_s[d][p];
                float diff = vv[cc] - zev;           // fl(z_q - z_e)
                ssel = fmaf(diff, diff, ssel);
                sm->e_s[d][p] = zev + diff;          // fl(z_e + fl(z_q - z_e))
            }
        }
#pragma unroll
        for (int o = 16; o; o >>= 1) ssel += __shfl_xor_sync(0xffffffffu, ssel, o);
        if ((tid & 31) == 0) atomicAdd(&g_sse, ssel);
    }
    __syncthreads();

    // ---- write z_q_st, coalesced over hw ----
    float* zo = out + (size_t)b * D_DIM * HW + hw0;
    for (int f = tid; f < D_DIM * TM; f += 256) {
        int d = f >> 7, p = f & 127;
        zo[d * HW + p] = sm->e_s[d][p];
    }
}

// ---------------------------------------------------------------------------
// Kernel 3: finalize — usage, perplexity, vq_loss
// ---------------------------------------------------------------------------
__global__ void vq_final(float* __restrict__ out) {
    __shared__ float red[32];
    int t = threadIdx.x;
    float u = (float)g_counts[t] / 32768.0f;
    out[OFS_USAGE + t] = u;
    float h = u * logf(u + 1e-10f);
#pragma unroll
    for (int o = 16; o; o >>= 1) h += __shfl_xor_sync(0xffffffffu, h, o);
    if ((t & 31) == 0) red[t >> 5] = h;
    __syncthreads();
    if (t < 32) {
        float v = red[t];
#pragma unroll
        for (int o = 16; o; o >>= 1) v += __shfl_xor_sync(0xffffffffu, v, o);
        if (t == 0) {
            out[OFS_PPL] = expf(-v);
            float m = g_sse / 2097152.0f;
            out[OFS_LOSS] = m + 0.25f * m;
        }
    }
}

// ---------------------------------------------------------------------------
extern "C" void kernel_launch(void* const* d_in, const int* in_sizes, int n_in,
                              void* d_out, int out_size) {
    const float* a0 = (const float*)d_in[0];
    const float* a1 = (const float*)d_in[1];
    const float* ze = a0;
    const float* cb = a1;
    if (n_in >= 2 && in_sizes[0] == KCODES * D_DIM) { ze = a1; cb = a0; }
    float* out = (float*)d_out;

    static_assert(sizeof(SmemLayout) < 100 * 1024, "smem layout too big");
    cudaFuncSetAttribute(vq_main, cudaFuncAttributeMaxDynamicSharedMemorySize,
                         (int)sizeof(SmemLayout));

    vq_prep<<<4, 256>>>(cb);
    vq_main<<<NTILES, 256, sizeof(SmemLayout)>>>(ze, cb, out);
    vq_final<<<1, 1024>>>(out);
}